// round 8
// baseline (speedup 1.0000x reference)
#include <cuda_runtime.h>
#include <cstdint>

// Problem constants (fixed by dataset).
#define N_NODES   400000
#define N_GRAPHS  1000
#define FEAT      240     // 64*1 + 32*3 + 16*5
#define NINST     112     // 64 + 32 + 16 irrep instances
#define NPAD      128     // NINST padded to power of 2 for cheap task decode
#define NB        8       // nodes staged per tile in pooling kernel

// ---------------------------------------------------------------------------
// Scratch (static device globals — no allocation allowed).
// Zero-initialized at module load; k_scan re-zeroes g_counts at end of every
// call, so the "counts are zero at k_hist entry" invariant holds for all
// replays (graph-capture safe, deterministic: every call does identical work).
// ---------------------------------------------------------------------------
__device__ int g_counts[N_GRAPHS];
__device__ int g_offs[N_GRAPHS + 1];
__device__ int g_cursor[N_GRAPHS];
__device__ int g_perm[N_NODES];

// ---------------------------------------------------------------------------
// K1: histogram of graph indices, 4 nodes/thread
// ---------------------------------------------------------------------------
#define HIST_BLK 1024
#define HIST_PER 4
__global__ __launch_bounds__(HIST_BLK) void k_hist(const int* __restrict__ index)
{
    int base = blockIdx.x * (HIST_BLK * HIST_PER);
    #pragma unroll
    for (int r = 0; r < HIST_PER; r++) {
        int n = base + r * HIST_BLK + threadIdx.x;
        if (n < N_NODES) atomicAdd(&g_counts[index[n]], 1);
    }
}

// ---------------------------------------------------------------------------
// K2: exclusive scan over 1000 counts (single block), then zero the counts
// for the next call.
// ---------------------------------------------------------------------------
__global__ void k_scan()
{
    __shared__ int s[1024];
    int tid = threadIdx.x;
    int c = (tid < N_GRAPHS) ? g_counts[tid] : 0;
    s[tid] = c;
    __syncthreads();
    #pragma unroll
    for (int off = 1; off < 1024; off <<= 1) {
        int v = (tid >= off) ? s[tid - off] : 0;
        __syncthreads();
        s[tid] += v;
        __syncthreads();
    }
    if (tid < N_GRAPHS) {
        int excl = s[tid] - c;
        g_offs[tid]   = excl;
        g_cursor[tid] = excl;
        g_counts[tid] = 0;               // reset for next call
    }
    if (tid == 0) g_offs[N_GRAPHS] = s[N_GRAPHS - 1];
}

// ---------------------------------------------------------------------------
// K3: scatter with per-block smem rank aggregation (counting sort).
// 4096 nodes per block -> ~980 global atomics per block instead of 4096.
// ---------------------------------------------------------------------------
#define SCAT_BLK  1024
#define SCAT_PER  4
#define SCAT_SPAN (SCAT_BLK * SCAT_PER)   // 4096
__global__ __launch_bounds__(SCAT_BLK) void k_scatter(const int* __restrict__ index)
{
    __shared__ int cnt [N_GRAPHS];
    __shared__ int base[N_GRAPHS];
    const int tid  = threadIdx.x;
    const int nbeg = blockIdx.x * SCAT_SPAN;

    for (int i = tid; i < N_GRAPHS; i += SCAT_BLK) cnt[i] = 0;
    __syncthreads();

    int myg[SCAT_PER], myrank[SCAT_PER];
    #pragma unroll
    for (int r = 0; r < SCAT_PER; r++) {
        int n = nbeg + r * SCAT_BLK + tid;
        if (n < N_NODES) {
            myg[r]    = index[n];
            myrank[r] = atomicAdd(&cnt[myg[r]], 1);
        } else myg[r] = -1;
    }
    __syncthreads();

    for (int i = tid; i < N_GRAPHS; i += SCAT_BLK) {
        int ci = cnt[i];
        if (ci > 0) base[i] = atomicAdd(&g_cursor[i], ci);
    }
    __syncthreads();

    #pragma unroll
    for (int r = 0; r < SCAT_PER; r++) {
        if (myg[r] >= 0) {
            int n = nbeg + r * SCAT_BLK + tid;
            g_perm[base[myg[r]] + myrank[r]] = n;
        }
    }
}

// ---------------------------------------------------------------------------
// K4: per-graph pooling + o3.Linear epilogue, fused. One CTA (256 th) per graph.
// __launch_bounds__(256, 7): 7 CTAs/SM guarantees all 1000 CTAs in ONE wave
// (needs regs <= 36). Double-buffered pipelined staging, packed float2 softmax
// weights, register accumulators, zero global atomics, single read of x.
// ---------------------------------------------------------------------------
__global__ __launch_bounds__(256, 7) void k_pool(const float* __restrict__ x,
                                                 const float* __restrict__ W0,
                                                 const float* __restrict__ W1,
                                                 const float* __restrict__ W2,
                                                 const float* __restrict__ b0,
                                                 float* __restrict__ out)
{
    const int g   = blockIdx.x;
    const int tid = threadIdx.x;
    const int beg = g_offs[g];
    const int end = g_offs[g + 1];
    const int cnt = end - beg;

    __shared__ float  xs [2][NB][FEAT];     // double-buffered node tiles (15.0 KB)
    __shared__ float2 ypm[NB][NPAD];        // (exp(+n), exp(-n)) packed   ( 8.0 KB)
    __shared__ float  totY[2 * NINST];
    // epilogue buffer aliases ypm (dead after the mainloop): 720 floats <= 2048
    float* c = reinterpret_cast<float*>(ypm);

    // irrep instance owning feature t
    const int t  = tid;
    const int kt = (t < 64) ? t : (t < 160 ? 64 + (t - 64) / 3 : 96 + (t - 160) / 5);

    float accS = 0.f, accP = 0.f, accM = 0.f;   // per-feature sums   (t < 240)
    float accYp = 0.f, accYm = 0.f;             // per-instance sums  (t < 112)

    // staging decomposition: NB*60=480 float4 = 2 per thread (2nd masked >=480)
    const int j0 = tid / 60,         v0 = tid % 60;
    const int j1 = (tid + 256) / 60, v1 = (tid + 256) % 60;
    const bool has1 = (tid + 256) < NB * 60;

    const int nIter = (cnt + NB - 1) / NB;
    int cur = 0;

    // ---- prologue: load + stage tile 0; pre-load perm indices for tile 1 ----
    if (nIter > 0) {
        const int nv0 = min(NB, cnt);
        float4 a, b;
        bool l0 = (j0 < nv0);
        bool l1 = has1 && (j1 < nv0);
        if (l0) a = reinterpret_cast<const float4*>(x + (size_t)g_perm[beg + j0] * FEAT)[v0];
        if (l1) b = reinterpret_cast<const float4*>(x + (size_t)g_perm[beg + j1] * FEAT)[v1];
        if (l0) reinterpret_cast<float4*>(xs[0][j0])[v0] = a;
        if (l1) reinterpret_cast<float4*>(xs[0][j1])[v1] = b;
    }
    int np0 = 0, np1 = 0;
    bool npl0 = false, npl1 = false;
    if (nIter > 1) {
        const int nbase = beg + NB;
        const int nvn   = min(NB, end - nbase);
        npl0 = (j0 < nvn);
        npl1 = has1 && (j1 < nvn);
        if (npl0) np0 = g_perm[nbase + j0];
        if (npl1) np1 = g_perm[nbase + j1];
    }
    __syncthreads();

    for (int it = 0; it < nIter; it++) {
        const int base   = beg + it * NB;
        const int nvalid = min(NB, end - base);

        // ---- issue next-tile x prefetch immediately (addresses pre-loaded) ----
        float4 pa, pb;
        const bool pl0 = npl0, pl1 = npl1;
        if (pl0) pa = reinterpret_cast<const float4*>(x + (size_t)np0 * FEAT)[v0];
        if (pl1) pb = reinterpret_cast<const float4*>(x + (size_t)np1 * FEAT)[v1];

        // ---- pre-load perm indices for tile it+2 (independent LDG) ----
        npl0 = npl1 = false;
        if (it + 2 < nIter) {
            const int nbase = base + 2 * NB;
            const int nvn   = min(NB, end - nbase);
            npl0 = (j0 < nvn);
            npl1 = has1 && (j1 < nvn);
            if (npl0) np0 = g_perm[nbase + j0];
            if (npl1) np1 = g_perm[nbase + j1];
        }

        const float (*xc)[FEAT] = xs[cur];

        // ---- per-instance norms -> packed (exp(+n), exp(-n)) ----
        // NB*NPAD = 1024 tasks / 256 threads = 4 per thread; shift/mask decode.
        #pragma unroll
        for (int r = 0; r < (NB * NPAD) / 256; r++) {
            int task = tid + r * 256;
            int j = task >> 7, k = task & (NPAD - 1);
            if (k < NINST && j < nvalid) {
                int s, d;
                if (k < 64)      { s = k;                  d = 1; }
                else if (k < 96) { s = 64 + 3 * (k - 64);  d = 3; }
                else             { s = 160 + 5 * (k - 96); d = 5; }
                float q = 0.f;
                #pragma unroll 5
                for (int e = 0; e < d; e++) { float u = xc[j][s + e]; q += u * u; }
                float ep = __expf(sqrtf(q));
                ypm[j][k] = make_float2(ep, __frcp_rn(ep));
            }
        }
        __syncthreads();

        // ---- register accumulation (fast path for full tiles) ----
        if (nvalid == NB) {
            if (t < FEAT) {
                #pragma unroll
                for (int j = 0; j < NB; j++) {
                    float2 q = ypm[j][kt];       // one LDS.64 per node
                    float  v = xc[j][t];
                    accS += v;
                    accP += v * q.x;
                    accM += v * q.y;
                }
            }
            if (t < NINST) {
                #pragma unroll
                for (int j = 0; j < NB; j++) {
                    float2 q = ypm[j][t];
                    accYp += q.x; accYm += q.y;
                }
            }
        } else {
            if (t < FEAT) {
                for (int j = 0; j < nvalid; j++) {
                    float2 q = ypm[j][kt];
                    float  v = xc[j][t];
                    accS += v;
                    accP += v * q.x;
                    accM += v * q.y;
                }
            }
            if (t < NINST) {
                for (int j = 0; j < nvalid; j++) {
                    float2 q = ypm[j][t];
                    accYp += q.x; accYm += q.y;
                }
            }
        }

        // ---- stage prefetched tile into the alternate buffer ----
        // (safe: buf[cur^1] was last read before the end barrier of it-1)
        if (pl0) reinterpret_cast<float4*>(xs[cur ^ 1][j0])[v0] = pa;
        if (pl1) reinterpret_cast<float4*>(xs[cur ^ 1][j1])[v1] = pb;
        __syncthreads();
        cur ^= 1;
    }

    if (t < NINST) { totY[t] = accYp; totY[NINST + t] = accYm; }
    __syncthreads();

    // ---- finalize pooled features into c[720] (aliases ypm — dead now) ----
    if (t < FEAT) {
        if (cnt == 0) {
            c[t] = 0.f; c[240 + t] = 0.f; c[480 + t] = 0.f;
        } else {
            c[t]       = accS / (float)cnt;
            c[240 + t] = accP / totY[kt];
            c[480 + t] = accM / totY[NINST + kt];
        }
    }
    __syncthreads();

    // ---- fused o3.Linear epilogue: thread t -> output feature t ----
    if (t >= FEAT) return;
    float acc = 0.f;

    if (t < 64) {
        // group 0e: cat[192] @ W0[192,64] / sqrt(192) + b0
        #pragma unroll 4
        for (int i = 0; i < 64; i++) {
            acc += c[i]       * __ldg(&W0[i * 64 + t]);
            acc += c[240 + i] * __ldg(&W0[(64 + i) * 64 + t]);
            acc += c[480 + i] * __ldg(&W0[(128 + i) * 64 + t]);
        }
        out[(size_t)g * FEAT + t] = acc * rsqrtf(192.f) + __ldg(&b0[t]);
    } else if (t < 160) {
        // group 1o: cat[96,3] @ W1[96,32] / sqrt(96)
        int cc = t - 64, o = cc / 3, dd = cc % 3;
        #pragma unroll 4
        for (int i = 0; i < 32; i++) {
            acc += c[64 + i * 3 + dd]       * __ldg(&W1[i * 32 + o]);
            acc += c[240 + 64 + i * 3 + dd] * __ldg(&W1[(32 + i) * 32 + o]);
            acc += c[480 + 64 + i * 3 + dd] * __ldg(&W1[(64 + i) * 32 + o]);
        }
        out[(size_t)g * FEAT + t] = acc * rsqrtf(96.f);
    } else {
        // group 2e: cat[48,5] @ W2[48,16] / sqrt(48)
        int cc = t - 160, o = cc / 5, dd = cc % 5;
        #pragma unroll 4
        for (int i = 0; i < 16; i++) {
            acc += c[160 + i * 5 + dd]       * __ldg(&W2[i * 16 + o]);
            acc += c[240 + 160 + i * 5 + dd] * __ldg(&W2[(16 + i) * 16 + o]);
            acc += c[480 + 160 + i * 5 + dd] * __ldg(&W2[(32 + i) * 16 + o]);
        }
        out[(size_t)g * FEAT + t] = acc * rsqrtf(48.f);
    }
}

// ---------------------------------------------------------------------------
// Launch: hist -> scan(+reset) -> scatter -> pool   (4 launches per call)
// ---------------------------------------------------------------------------
extern "C" void kernel_launch(void* const* d_in, const int* in_sizes, int n_in,
                              void* d_out, int out_size)
{
    const float* x     = nullptr;
    const int*   index = nullptr;
    const float *W0 = nullptr, *W1 = nullptr, *W2 = nullptr, *b0 = nullptr;

    for (int i = 0; i < n_in; i++) {
        switch (in_sizes[i]) {
            case 96000000: x     = (const float*)d_in[i]; break;
            case 400000:   index = (const int*)  d_in[i]; break;
            case 12288:    W0    = (const float*)d_in[i]; break;
            case 3072:     W1    = (const float*)d_in[i]; break;
            case 768:      W2    = (const float*)d_in[i]; break;
            case 64:       b0    = (const float*)d_in[i]; break;
            default: break;  // dim_size scalar etc.
        }
    }

    float* out = (float*)d_out;
    (void)out_size;

    k_hist   <<<(N_NODES + HIST_BLK * HIST_PER - 1) / (HIST_BLK * HIST_PER), HIST_BLK>>>(index);
    k_scan   <<<1, 1024>>>();
    k_scatter<<<(N_NODES + SCAT_SPAN - 1) / SCAT_SPAN, SCAT_BLK>>>(index);
    k_pool   <<<N_GRAPHS, 256>>>(x, W0, W1, W2, b0, out);
}

// round 11
// speedup vs baseline: 1.9037x; 1.9037x over previous
#include <cuda_runtime.h>
#include <cstdint>

// Problem constants (fixed by dataset).
#define N_NODES   400000
#define N_GRAPHS  1000
#define FEAT      240     // 64*1 + 32*3 + 16*5
#define NINST     112     // 64 + 32 + 16 irrep instances

// ---------------------------------------------------------------------------
// Scratch (static device globals — no allocation allowed).
// Zero-initialized at load; k_scan re-zeroes g_counts every call, so the
// "counts are zero at k_hist entry" invariant holds on all graph replays.
// ---------------------------------------------------------------------------
__device__ int g_counts[N_GRAPHS];
__device__ int g_offs[N_GRAPHS + 1];
__device__ int g_cursor[N_GRAPHS];
__device__ int g_perm[N_NODES];

// ---------------------------------------------------------------------------
// K1: histogram with per-block smem aggregation (~1000 global atomics/block)
// ---------------------------------------------------------------------------
#define HIST_BLK 1024
#define HIST_PER 4
__global__ __launch_bounds__(HIST_BLK) void k_hist(const int* __restrict__ index)
{
    __shared__ int h[N_GRAPHS];
    const int tid = threadIdx.x;
    for (int i = tid; i < N_GRAPHS; i += HIST_BLK) h[i] = 0;
    __syncthreads();
    int base = blockIdx.x * (HIST_BLK * HIST_PER);
    #pragma unroll
    for (int r = 0; r < HIST_PER; r++) {
        int n = base + r * HIST_BLK + tid;
        if (n < N_NODES) atomicAdd(&h[index[n]], 1);
    }
    __syncthreads();
    for (int i = tid; i < N_GRAPHS; i += HIST_BLK) {
        int ci = h[i];
        if (ci > 0) atomicAdd(&g_counts[i], ci);
    }
}

// ---------------------------------------------------------------------------
// K2: exclusive scan over 1000 counts (single block), then zero the counts.
// ---------------------------------------------------------------------------
__global__ void k_scan()
{
    __shared__ int s[1024];
    int tid = threadIdx.x;
    int c = (tid < N_GRAPHS) ? g_counts[tid] : 0;
    s[tid] = c;
    __syncthreads();
    #pragma unroll
    for (int off = 1; off < 1024; off <<= 1) {
        int v = (tid >= off) ? s[tid - off] : 0;
        __syncthreads();
        s[tid] += v;
        __syncthreads();
    }
    if (tid < N_GRAPHS) {
        int excl = s[tid] - c;
        g_offs[tid]   = excl;
        g_cursor[tid] = excl;
        g_counts[tid] = 0;               // reset for next call
    }
    if (tid == 0) g_offs[N_GRAPHS] = s[N_GRAPHS - 1];
}

// ---------------------------------------------------------------------------
// K3: scatter with per-block smem rank aggregation (counting sort).
// ---------------------------------------------------------------------------
#define SCAT_BLK  1024
#define SCAT_PER  4
#define SCAT_SPAN (SCAT_BLK * SCAT_PER)   // 4096
__global__ __launch_bounds__(SCAT_BLK) void k_scatter(const int* __restrict__ index)
{
    __shared__ int cnt [N_GRAPHS];
    __shared__ int base[N_GRAPHS];
    const int tid  = threadIdx.x;
    const int nbeg = blockIdx.x * SCAT_SPAN;

    for (int i = tid; i < N_GRAPHS; i += SCAT_BLK) cnt[i] = 0;
    __syncthreads();

    int myg[SCAT_PER], myrank[SCAT_PER];
    #pragma unroll
    for (int r = 0; r < SCAT_PER; r++) {
        int n = nbeg + r * SCAT_BLK + tid;
        if (n < N_NODES) {
            myg[r]    = index[n];
            myrank[r] = atomicAdd(&cnt[myg[r]], 1);
        } else myg[r] = -1;
    }
    __syncthreads();

    for (int i = tid; i < N_GRAPHS; i += SCAT_BLK) {
        int ci = cnt[i];
        if (ci > 0) base[i] = atomicAdd(&g_cursor[i], ci);
    }
    __syncthreads();

    #pragma unroll
    for (int r = 0; r < SCAT_PER; r++) {
        if (myg[r] >= 0) {
            int n = nbeg + r * SCAT_BLK + tid;
            g_perm[base[myg[r]] + myrank[r]] = n;
        }
    }
}

// ---------------------------------------------------------------------------
// K4: instance-per-thread PNA pooling + o3.Linear epilogue. One CTA per graph.
// 256 threads = 2 teams x 4 warps; team t processes nodes beg+t, step 2.
// Within a team (tw = wid&3):
//   tw 0,1        : l=0 scalar, feat f = tw*32+lane    (64 feats)
//   tw 2          : l=1 instance k=lane, f0 = 64+3*lane (32 inst x 3)
//   tw 3, lane<16 : l=2 instance k=lane, f0 = 160+5*lane (16 inst x 5)
// Norms are thread-local (NO shuffles, NO smem, NO barriers in mainloop).
// Teams merge partials through smem at the end (2 barriers total).
// ---------------------------------------------------------------------------
__global__ __launch_bounds__(256) void k_pool(const float* __restrict__ x,
                                              const float* __restrict__ W0,
                                              const float* __restrict__ W1,
                                              const float* __restrict__ W2,
                                              const float* __restrict__ b0,
                                              float* __restrict__ out)
{
    const int g    = blockIdx.x;
    const int tid  = threadIdx.x;
    const int wid  = tid >> 5;
    const int lane = tid & 31;
    const int team = wid >> 2;          // 0 or 1
    const int tw   = wid & 3;           // team-local warp
    const int beg  = g_offs[g];
    const int end  = g_offs[g + 1];
    const int cnt  = end - beg;

    __shared__ float sS[FEAT], sP[FEAT], sM[FEAT];   // team-1 partial sums
    __shared__ float sYp[NINST], sYm[NINST];
    __shared__ float c[720];            // mean[240] | softmax[240] | softmin[240]

    // ---------------- mainloop (branch per role; d compile-time) ----------
    if (tw < 2) {
        // ----- l = 0 : scalar features -----
        const int f = tw * 32 + lane;                 // 0..63
        const float* xf = x + f;
        float aS = 0.f, aP = 0.f, aM = 0.f, aYp = 0.f, aYm = 0.f;
        int i = beg + team;
        for (; i + 6 < end; i += 8) {                 // 4 nodes per iter (step 2)
            int n0 = g_perm[i], n1 = g_perm[i + 2], n2 = g_perm[i + 4], n3 = g_perm[i + 6];
            float v0 = xf[(size_t)n0 * FEAT], v1 = xf[(size_t)n1 * FEAT];
            float v2 = xf[(size_t)n2 * FEAT], v3 = xf[(size_t)n3 * FEAT];
            float v[4] = {v0, v1, v2, v3};
            #pragma unroll
            for (int u = 0; u < 4; u++) {
                float ep = __expf(fabsf(v[u]));
                float em = __frcp_rn(ep);
                aS += v[u]; aP += v[u] * ep; aM += v[u] * em; aYp += ep; aYm += em;
            }
        }
        for (; i < end; i += 2) {
            float v = xf[(size_t)g_perm[i] * FEAT];
            float ep = __expf(fabsf(v));
            float em = __frcp_rn(ep);
            aS += v; aP += v * ep; aM += v * em; aYp += ep; aYm += em;
        }
        if (team == 1) {
            sS[f] = aS; sP[f] = aP; sM[f] = aM; sYp[f] = aYp; sYm[f] = aYm;
        }
        __syncthreads();
        if (team == 0) {
            if (cnt == 0) { c[f] = 0.f; c[240 + f] = 0.f; c[480 + f] = 0.f; }
            else {
                c[f]       = (aS + sS[f]) / (float)cnt;
                c[240 + f] = (aP + sP[f]) / (aYp + sYp[f]);
                c[480 + f] = (aM + sM[f]) / (aYm + sYm[f]);
            }
        }
    } else if (tw == 2) {
        // ----- l = 1 : 3-component instances -----
        const int k  = lane;                          // instance 0..31
        const int f0 = 64 + 3 * lane;
        const float* xf = x + f0;
        float aS[3] = {0,0,0}, aP[3] = {0,0,0}, aM[3] = {0,0,0};
        float aYp = 0.f, aYm = 0.f;
        int i = beg + team;
        for (; i + 2 < end; i += 4) {                 // 2 nodes per iter
            int n0 = g_perm[i], n1 = g_perm[i + 2];
            const float* r0 = xf + (size_t)n0 * FEAT;
            const float* r1 = xf + (size_t)n1 * FEAT;
            float v0[3] = {r0[0], r0[1], r0[2]};
            float v1[3] = {r1[0], r1[1], r1[2]};
            {
                float q = v0[0]*v0[0] + v0[1]*v0[1] + v0[2]*v0[2];
                float ep = __expf(sqrtf(q)), em = __frcp_rn(ep);
                #pragma unroll
                for (int e = 0; e < 3; e++) { aS[e] += v0[e]; aP[e] += v0[e]*ep; aM[e] += v0[e]*em; }
                aYp += ep; aYm += em;
            }
            {
                float q = v1[0]*v1[0] + v1[1]*v1[1] + v1[2]*v1[2];
                float ep = __expf(sqrtf(q)), em = __frcp_rn(ep);
                #pragma unroll
                for (int e = 0; e < 3; e++) { aS[e] += v1[e]; aP[e] += v1[e]*ep; aM[e] += v1[e]*em; }
                aYp += ep; aYm += em;
            }
        }
        for (; i < end; i += 2) {
            const float* r = xf + (size_t)g_perm[i] * FEAT;
            float v[3] = {r[0], r[1], r[2]};
            float q = v[0]*v[0] + v[1]*v[1] + v[2]*v[2];
            float ep = __expf(sqrtf(q)), em = __frcp_rn(ep);
            #pragma unroll
            for (int e = 0; e < 3; e++) { aS[e] += v[e]; aP[e] += v[e]*ep; aM[e] += v[e]*em; }
            aYp += ep; aYm += em;
        }
        if (team == 1) {
            #pragma unroll
            for (int e = 0; e < 3; e++) { sS[f0+e] = aS[e]; sP[f0+e] = aP[e]; sM[f0+e] = aM[e]; }
            sYp[64 + k] = aYp; sYm[64 + k] = aYm;
        }
        __syncthreads();
        if (team == 0) {
            if (cnt == 0) {
                #pragma unroll
                for (int e = 0; e < 3; e++) { c[f0+e] = 0.f; c[240+f0+e] = 0.f; c[480+f0+e] = 0.f; }
            } else {
                float yp = aYp + sYp[64 + k], ym = aYm + sYm[64 + k];
                float icnt = 1.f / (float)cnt, iyp = 1.f / yp, iym = 1.f / ym;
                #pragma unroll
                for (int e = 0; e < 3; e++) {
                    c[f0+e]       = (aS[e] + sS[f0+e]) * icnt;
                    c[240+f0+e]   = (aP[e] + sP[f0+e]) * iyp;
                    c[480+f0+e]   = (aM[e] + sM[f0+e]) * iym;
                }
            }
        }
    } else {
        // ----- l = 2 : 5-component instances (lanes 0..15 active) -----
        const bool act = (lane < 16);
        const int  k   = lane;
        const int  f0  = act ? (160 + 5 * lane) : 160;
        const float* xf = x + f0;
        float aS[5] = {0,0,0,0,0}, aP[5] = {0,0,0,0,0}, aM[5] = {0,0,0,0,0};
        float aYp = 0.f, aYm = 0.f;
        if (act) {
            int i = beg + team;
            for (; i + 2 < end; i += 4) {             // 2 nodes per iter
                int n0 = g_perm[i], n1 = g_perm[i + 2];
                const float* r0 = xf + (size_t)n0 * FEAT;
                const float* r1 = xf + (size_t)n1 * FEAT;
                float v0[5] = {r0[0], r0[1], r0[2], r0[3], r0[4]};
                float v1[5] = {r1[0], r1[1], r1[2], r1[3], r1[4]};
                {
                    float q = v0[0]*v0[0] + v0[1]*v0[1] + v0[2]*v0[2] + v0[3]*v0[3] + v0[4]*v0[4];
                    float ep = __expf(sqrtf(q)), em = __frcp_rn(ep);
                    #pragma unroll
                    for (int e = 0; e < 5; e++) { aS[e] += v0[e]; aP[e] += v0[e]*ep; aM[e] += v0[e]*em; }
                    aYp += ep; aYm += em;
                }
                {
                    float q = v1[0]*v1[0] + v1[1]*v1[1] + v1[2]*v1[2] + v1[3]*v1[3] + v1[4]*v1[4];
                    float ep = __expf(sqrtf(q)), em = __frcp_rn(ep);
                    #pragma unroll
                    for (int e = 0; e < 5; e++) { aS[e] += v1[e]; aP[e] += v1[e]*ep; aM[e] += v1[e]*em; }
                    aYp += ep; aYm += em;
                }
            }
            for (; i < end; i += 2) {
                const float* r = xf + (size_t)g_perm[i] * FEAT;
                float v[5] = {r[0], r[1], r[2], r[3], r[4]};
                float q = v[0]*v[0] + v[1]*v[1] + v[2]*v[2] + v[3]*v[3] + v[4]*v[4];
                float ep = __expf(sqrtf(q)), em = __frcp_rn(ep);
                #pragma unroll
                for (int e = 0; e < 5; e++) { aS[e] += v[e]; aP[e] += v[e]*ep; aM[e] += v[e]*em; }
                aYp += ep; aYm += em;
            }
        }
        if (team == 1 && act) {
            #pragma unroll
            for (int e = 0; e < 5; e++) { sS[f0+e] = aS[e]; sP[f0+e] = aP[e]; sM[f0+e] = aM[e]; }
            sYp[96 + k] = aYp; sYm[96 + k] = aYm;
        }
        __syncthreads();
        if (team == 0 && act) {
            if (cnt == 0) {
                #pragma unroll
                for (int e = 0; e < 5; e++) { c[f0+e] = 0.f; c[240+f0+e] = 0.f; c[480+f0+e] = 0.f; }
            } else {
                float yp = aYp + sYp[96 + k], ym = aYm + sYm[96 + k];
                float icnt = 1.f / (float)cnt, iyp = 1.f / yp, iym = 1.f / ym;
                #pragma unroll
                for (int e = 0; e < 5; e++) {
                    c[f0+e]       = (aS[e] + sS[f0+e]) * icnt;
                    c[240+f0+e]   = (aP[e] + sP[f0+e]) * iyp;
                    c[480+f0+e]   = (aM[e] + sM[f0+e]) * iym;
                }
            }
        }
    }
    __syncthreads();

    // ---- fused o3.Linear epilogue: thread t -> output feature t ----
    const int t = tid;
    if (t >= FEAT) return;
    float acc = 0.f;

    if (t < 64) {
        // group 0e: cat[192] @ W0[192,64] / sqrt(192) + b0
        #pragma unroll 4
        for (int k = 0; k < 64; k++) {
            acc += c[k]       * __ldg(&W0[k * 64 + t]);
            acc += c[240 + k] * __ldg(&W0[(64 + k) * 64 + t]);
            acc += c[480 + k] * __ldg(&W0[(128 + k) * 64 + t]);
        }
        out[(size_t)g * FEAT + t] = acc * rsqrtf(192.f) + __ldg(&b0[t]);
    } else if (t < 160) {
        // group 1o: cat[96,3] @ W1[96,32] / sqrt(96)
        int cc = t - 64, o = cc / 3, dd = cc % 3;
        #pragma unroll 4
        for (int k = 0; k < 32; k++) {
            acc += c[64 + k * 3 + dd]       * __ldg(&W1[k * 32 + o]);
            acc += c[240 + 64 + k * 3 + dd] * __ldg(&W1[(32 + k) * 32 + o]);
            acc += c[480 + 64 + k * 3 + dd] * __ldg(&W1[(64 + k) * 32 + o]);
        }
        out[(size_t)g * FEAT + t] = acc * rsqrtf(96.f);
    } else {
        // group 2e: cat[48,5] @ W2[48,16] / sqrt(48)
        int cc = t - 160, o = cc / 5, dd = cc % 5;
        #pragma unroll 4
        for (int k = 0; k < 16; k++) {
            acc += c[160 + k * 5 + dd]       * __ldg(&W2[k * 16 + o]);
            acc += c[240 + 160 + k * 5 + dd] * __ldg(&W2[(16 + k) * 16 + o]);
            acc += c[480 + 160 + k * 5 + dd] * __ldg(&W2[(32 + k) * 16 + o]);
        }
        out[(size_t)g * FEAT + t] = acc * rsqrtf(48.f);
    }
}

// ---------------------------------------------------------------------------
// Launch: hist -> scan(+reset) -> scatter -> pool   (4 launches per call)
// ---------------------------------------------------------------------------
extern "C" void kernel_launch(void* const* d_in, const int* in_sizes, int n_in,
                              void* d_out, int out_size)
{
    const float* x     = nullptr;
    const int*   index = nullptr;
    const float *W0 = nullptr, *W1 = nullptr, *W2 = nullptr, *b0 = nullptr;

    for (int i = 0; i < n_in; i++) {
        switch (in_sizes[i]) {
            case 96000000: x     = (const float*)d_in[i]; break;
            case 400000:   index = (const int*)  d_in[i]; break;
            case 12288:    W0    = (const float*)d_in[i]; break;
            case 3072:     W1    = (const float*)d_in[i]; break;
            case 768:      W2    = (const float*)d_in[i]; break;
            case 64:       b0    = (const float*)d_in[i]; break;
            default: break;  // dim_size scalar etc.
        }
    }

    float* out = (float*)d_out;
    (void)out_size;

    k_hist   <<<(N_NODES + HIST_BLK * HIST_PER - 1) / (HIST_BLK * HIST_PER), HIST_BLK>>>(index);
    k_scan   <<<1, 1024>>>();
    k_scatter<<<(N_NODES + SCAT_SPAN - 1) / SCAT_SPAN, SCAT_BLK>>>(index);
    k_pool   <<<N_GRAPHS, 256>>>(x, W0, W1, W2, b0, out);
}

// round 14
// speedup vs baseline: 2.2969x; 1.2065x over previous
#include <cuda_runtime.h>
#include <cstdint>

// Problem constants (fixed by dataset).
#define N_NODES   400000
#define N_GRAPHS  1000
#define FEAT      240     // 64*1 + 32*3 + 16*5
#define NINST     112     // 64 + 32 + 16 irrep instances
#define SPLITS    3       // CTAs per graph in k_pool
#define ST        (SPLITS * 2)   // node stride: splits x 2 teams = 6
#define REC       944     // partial record: S[240] P[240] M[240] Yp[112] Ym[112]
#define R_S       0
#define R_P       240
#define R_M       480
#define R_YP      720
#define R_YM      832

// ---------------------------------------------------------------------------
// Scratch (static device globals — no allocation allowed).
// ---------------------------------------------------------------------------
__device__ int   g_counts[N_GRAPHS];
__device__ int   g_offs[N_GRAPHS + 1];
__device__ int   g_cursor[N_GRAPHS];
__device__ int   g_perm[N_NODES];
__device__ float g_part[N_GRAPHS * SPLITS][REC];   // ~11.3 MB partial sums

// ---------------------------------------------------------------------------
// K1: histogram with per-block smem aggregation
// ---------------------------------------------------------------------------
#define HIST_BLK 1024
#define HIST_PER 4
__global__ __launch_bounds__(HIST_BLK) void k_hist(const int* __restrict__ index)
{
    __shared__ int h[N_GRAPHS];
    const int tid = threadIdx.x;
    for (int i = tid; i < N_GRAPHS; i += HIST_BLK) h[i] = 0;
    __syncthreads();
    int base = blockIdx.x * (HIST_BLK * HIST_PER);
    #pragma unroll
    for (int r = 0; r < HIST_PER; r++) {
        int n = base + r * HIST_BLK + tid;
        if (n < N_NODES) atomicAdd(&h[index[n]], 1);
    }
    __syncthreads();
    for (int i = tid; i < N_GRAPHS; i += HIST_BLK) {
        int ci = h[i];
        if (ci > 0) atomicAdd(&g_counts[i], ci);
    }
}

// ---------------------------------------------------------------------------
// K2: exclusive scan over 1000 counts (single block), then zero the counts.
// ---------------------------------------------------------------------------
__global__ void k_scan()
{
    __shared__ int s[1024];
    int tid = threadIdx.x;
    int c = (tid < N_GRAPHS) ? g_counts[tid] : 0;
    s[tid] = c;
    __syncthreads();
    #pragma unroll
    for (int off = 1; off < 1024; off <<= 1) {
        int v = (tid >= off) ? s[tid - off] : 0;
        __syncthreads();
        s[tid] += v;
        __syncthreads();
    }
    if (tid < N_GRAPHS) {
        int excl = s[tid] - c;
        g_offs[tid]   = excl;
        g_cursor[tid] = excl;
        g_counts[tid] = 0;               // reset for next call
    }
    if (tid == 0) g_offs[N_GRAPHS] = s[N_GRAPHS - 1];
}

// ---------------------------------------------------------------------------
// K3: scatter with per-block smem rank aggregation (counting sort).
// ---------------------------------------------------------------------------
#define SCAT_BLK  1024
#define SCAT_PER  4
#define SCAT_SPAN (SCAT_BLK * SCAT_PER)   // 4096
__global__ __launch_bounds__(SCAT_BLK) void k_scatter(const int* __restrict__ index)
{
    __shared__ int cnt [N_GRAPHS];
    __shared__ int base[N_GRAPHS];
    const int tid  = threadIdx.x;
    const int nbeg = blockIdx.x * SCAT_SPAN;

    for (int i = tid; i < N_GRAPHS; i += SCAT_BLK) cnt[i] = 0;
    __syncthreads();

    int myg[SCAT_PER], myrank[SCAT_PER];
    #pragma unroll
    for (int r = 0; r < SCAT_PER; r++) {
        int n = nbeg + r * SCAT_BLK + tid;
        if (n < N_NODES) {
            myg[r]    = index[n];
            myrank[r] = atomicAdd(&cnt[myg[r]], 1);
        } else myg[r] = -1;
    }
    __syncthreads();

    for (int i = tid; i < N_GRAPHS; i += SCAT_BLK) {
        int ci = cnt[i];
        if (ci > 0) base[i] = atomicAdd(&g_cursor[i], ci);
    }
    __syncthreads();

    #pragma unroll
    for (int r = 0; r < SCAT_PER; r++) {
        if (myg[r] >= 0) {
            int n = nbeg + r * SCAT_BLK + tid;
            g_perm[base[myg[r]] + myrank[r]] = n;
        }
    }
}

// ---------------------------------------------------------------------------
// K4: partial PNA pooling. SPLITS CTAs per graph (grid = 3000); CTA (g, s)
// processes nodes at offsets s*2+team (mod 6). 256 threads = 2 teams x 4 warps:
//   tw 0,1        : l=0 scalar feature f = tw*32+lane, 8 nodes/iter
//   tw 2          : l=1 instance lane (3 comps),       4 nodes/iter
//   tw 3          : l=2 PAIR-SPLIT: lane k<16 -> comps 0-2 of inst k,
//                   lane k+16 -> comps 3-4; q merged via shfl_xor(16).
//                   All 32 lanes active, 2 nodes/iter.
// Thread-local norms otherwise; no smem/barrier in mainloops.
// Record (944 floats) written coalesced to g_part[bid].
// (Resubmission of R12 — prior round failed at device acquisition, pre-launch.)
// ---------------------------------------------------------------------------
__global__ __launch_bounds__(256) void k_pool(const float* __restrict__ x)
{
    const int bid  = blockIdx.x;
    const int g    = bid % N_GRAPHS;
    const int s    = bid / N_GRAPHS;    // split 0..2
    const int tid  = threadIdx.x;
    const int wid  = tid >> 5;
    const int lane = tid & 31;
    const int team = wid >> 2;          // 0 or 1
    const int tw   = wid & 3;           // team-local warp
    const int beg  = g_offs[g];
    const int end  = g_offs[g + 1];
    const unsigned FULL = 0xFFFFFFFFu;

    __shared__ float sbuf[REC];

    const int start = beg + s * 2 + team;   // residue (s*2+team) mod ST

    if (tw < 2) {
        // ----- l = 0 : scalar features, 8 nodes per iteration -----
        const int f = tw * 32 + lane;
        const float* xf = x + f;
        float aS = 0.f, aP = 0.f, aM = 0.f, aYp = 0.f, aYm = 0.f;
        int i = start;
        for (; i + 7 * ST < end; i += 8 * ST) {
            float v[8];
            #pragma unroll
            for (int u = 0; u < 8; u++)
                v[u] = xf[(size_t)g_perm[i + u * ST] * FEAT];
            #pragma unroll
            for (int u = 0; u < 8; u++) {
                float ep = __expf(fabsf(v[u]));
                float em = __frcp_rn(ep);
                aS += v[u]; aP += v[u] * ep; aM += v[u] * em; aYp += ep; aYm += em;
            }
        }
        for (; i < end; i += ST) {
            float v = xf[(size_t)g_perm[i] * FEAT];
            float ep = __expf(fabsf(v));
            float em = __frcp_rn(ep);
            aS += v; aP += v * ep; aM += v * em; aYp += ep; aYm += em;
        }
        if (team == 1) {
            sbuf[R_S + f] = aS; sbuf[R_P + f] = aP; sbuf[R_M + f] = aM;
            sbuf[R_YP + f] = aYp; sbuf[R_YM + f] = aYm;
        }
        __syncthreads();
        if (team == 0) {
            sbuf[R_S + f] += aS; sbuf[R_P + f] += aP; sbuf[R_M + f] += aM;
            sbuf[R_YP + f] += aYp; sbuf[R_YM + f] += aYm;
        }
    } else if (tw == 2) {
        // ----- l = 1 : 3-component instances, 4 nodes per iteration -----
        const int k  = lane;
        const int f0 = 64 + 3 * lane;
        const float* xf = x + f0;
        float aS[3] = {0,0,0}, aP[3] = {0,0,0}, aM[3] = {0,0,0};
        float aYp = 0.f, aYm = 0.f;
        int i = start;
        for (; i + 3 * ST < end; i += 4 * ST) {
            float v[4][3];
            #pragma unroll
            for (int u = 0; u < 4; u++) {
                const float* r = xf + (size_t)g_perm[i + u * ST] * FEAT;
                v[u][0] = r[0]; v[u][1] = r[1]; v[u][2] = r[2];
            }
            #pragma unroll
            for (int u = 0; u < 4; u++) {
                float q = v[u][0]*v[u][0] + v[u][1]*v[u][1] + v[u][2]*v[u][2];
                float ep = __expf(sqrtf(q)), em = __frcp_rn(ep);
                #pragma unroll
                for (int e = 0; e < 3; e++) {
                    aS[e] += v[u][e]; aP[e] += v[u][e]*ep; aM[e] += v[u][e]*em;
                }
                aYp += ep; aYm += em;
            }
        }
        for (; i < end; i += ST) {
            const float* r = xf + (size_t)g_perm[i] * FEAT;
            float v[3] = {r[0], r[1], r[2]};
            float q = v[0]*v[0] + v[1]*v[1] + v[2]*v[2];
            float ep = __expf(sqrtf(q)), em = __frcp_rn(ep);
            #pragma unroll
            for (int e = 0; e < 3; e++) { aS[e] += v[e]; aP[e] += v[e]*ep; aM[e] += v[e]*em; }
            aYp += ep; aYm += em;
        }
        if (team == 1) {
            #pragma unroll
            for (int e = 0; e < 3; e++) {
                sbuf[R_S + f0 + e] = aS[e]; sbuf[R_P + f0 + e] = aP[e]; sbuf[R_M + f0 + e] = aM[e];
            }
            sbuf[R_YP + 64 + k] = aYp; sbuf[R_YM + 64 + k] = aYm;
        }
        __syncthreads();
        if (team == 0) {
            #pragma unroll
            for (int e = 0; e < 3; e++) {
                sbuf[R_S + f0 + e] += aS[e]; sbuf[R_P + f0 + e] += aP[e]; sbuf[R_M + f0 + e] += aM[e];
            }
            sbuf[R_YP + 64 + k] += aYp; sbuf[R_YM + 64 + k] += aYm;
        }
    } else {
        // ----- l = 2 : pair-split over 32 lanes, 2 nodes per iteration -----
        // lane k<16: inst k comps 0..2; lane k+16: inst k comps 3..4.
        const bool lo = (lane < 16);
        const int  k  = lane & 15;
        const int  f0 = 160 + 5 * k;
        const int  nc = lo ? 3 : 2;                  // components this lane owns
        const float* xf = x + f0 + (lo ? 0 : 3);
        float aS[3] = {0,0,0}, aP[3] = {0,0,0}, aM[3] = {0,0,0};
        float aYp = 0.f, aYm = 0.f;
        int i = start;
        for (; i + ST < end; i += 2 * ST) {
            float v0[3] = {0,0,0}, v1[3] = {0,0,0};
            const float* r0 = xf + (size_t)g_perm[i] * FEAT;
            const float* r1 = xf + (size_t)g_perm[i + ST] * FEAT;
            v0[0] = r0[0]; v0[1] = r0[1]; if (lo) v0[2] = r0[2];
            v1[0] = r1[0]; v1[1] = r1[1]; if (lo) v1[2] = r1[2];
            {
                float qp = v0[0]*v0[0] + v0[1]*v0[1] + v0[2]*v0[2];
                float q  = qp + __shfl_xor_sync(FULL, qp, 16);
                float ep = __expf(sqrtf(q)), em = __frcp_rn(ep);
                #pragma unroll
                for (int e = 0; e < 3; e++) { aS[e] += v0[e]; aP[e] += v0[e]*ep; aM[e] += v0[e]*em; }
                if (lo) { aYp += ep; aYm += em; }
            }
            {
                float qp = v1[0]*v1[0] + v1[1]*v1[1] + v1[2]*v1[2];
                float q  = qp + __shfl_xor_sync(FULL, qp, 16);
                float ep = __expf(sqrtf(q)), em = __frcp_rn(ep);
                #pragma unroll
                for (int e = 0; e < 3; e++) { aS[e] += v1[e]; aP[e] += v1[e]*ep; aM[e] += v1[e]*em; }
                if (lo) { aYp += ep; aYm += em; }
            }
        }
        for (; i < end; i += ST) {
            float v[3] = {0,0,0};
            const float* r = xf + (size_t)g_perm[i] * FEAT;
            v[0] = r[0]; v[1] = r[1]; if (lo) v[2] = r[2];
            float qp = v[0]*v[0] + v[1]*v[1] + v[2]*v[2];
            float q  = qp + __shfl_xor_sync(FULL, qp, 16);
            float ep = __expf(sqrtf(q)), em = __frcp_rn(ep);
            #pragma unroll
            for (int e = 0; e < 3; e++) { aS[e] += v[e]; aP[e] += v[e]*ep; aM[e] += v[e]*em; }
            if (lo) { aYp += ep; aYm += em; }
        }
        const int fb = f0 + (lo ? 0 : 3);            // first feature this lane owns
        if (team == 1) {
            for (int e = 0; e < nc; e++) {
                sbuf[R_S + fb + e] = aS[e]; sbuf[R_P + fb + e] = aP[e]; sbuf[R_M + fb + e] = aM[e];
            }
            if (lo) { sbuf[R_YP + 96 + k] = aYp; sbuf[R_YM + 96 + k] = aYm; }
        }
        __syncthreads();
        if (team == 0) {
            for (int e = 0; e < nc; e++) {
                sbuf[R_S + fb + e] += aS[e]; sbuf[R_P + fb + e] += aP[e]; sbuf[R_M + fb + e] += aM[e];
            }
            if (lo) { sbuf[R_YP + 96 + k] += aYp; sbuf[R_YM + 96 + k] += aYm; }
        }
    }
    __syncthreads();

    // ---- write the partial record, coalesced ----
    for (int j = tid; j < REC; j += 256) g_part[bid][j] = sbuf[j];
}

// ---------------------------------------------------------------------------
// K5: merge SPLITS partials (fixed order -> deterministic), finalize pooled
// features, and apply the o3.Linear epilogue. One CTA per graph.
// ---------------------------------------------------------------------------
__global__ __launch_bounds__(256) void k_final(const float* __restrict__ W0,
                                               const float* __restrict__ W1,
                                               const float* __restrict__ W2,
                                               const float* __restrict__ b0,
                                               float* __restrict__ out)
{
    const int g   = blockIdx.x;
    const int tid = threadIdx.x;
    const int cnt = g_offs[g + 1] - g_offs[g];

    __shared__ float sbuf[REC];
    __shared__ float c[720];

    for (int j = tid; j < REC; j += 256)
        sbuf[j] = g_part[g][j] + g_part[N_GRAPHS + g][j] + g_part[2 * N_GRAPHS + g][j];
    __syncthreads();

    const int t = tid;
    if (t < FEAT) {
        const int kt = (t < 64) ? t : (t < 160 ? 64 + (t - 64) / 3 : 96 + (t - 160) / 5);
        if (cnt == 0) {
            c[t] = 0.f; c[240 + t] = 0.f; c[480 + t] = 0.f;
        } else {
            c[t]       = sbuf[R_S + t] / (float)cnt;
            c[240 + t] = sbuf[R_P + t] / sbuf[R_YP + kt];
            c[480 + t] = sbuf[R_M + t] / sbuf[R_YM + kt];
        }
    }
    __syncthreads();

    if (t >= FEAT) return;
    float acc = 0.f;

    if (t < 64) {
        // group 0e: cat[192] @ W0[192,64] / sqrt(192) + b0
        #pragma unroll 4
        for (int k = 0; k < 64; k++) {
            acc += c[k]       * __ldg(&W0[k * 64 + t]);
            acc += c[240 + k] * __ldg(&W0[(64 + k) * 64 + t]);
            acc += c[480 + k] * __ldg(&W0[(128 + k) * 64 + t]);
        }
        out[(size_t)g * FEAT + t] = acc * rsqrtf(192.f) + __ldg(&b0[t]);
    } else if (t < 160) {
        // group 1o: cat[96,3] @ W1[96,32] / sqrt(96)
        int cc = t - 64, o = cc / 3, dd = cc % 3;
        #pragma unroll 4
        for (int k = 0; k < 32; k++) {
            acc += c[64 + k * 3 + dd]       * __ldg(&W1[k * 32 + o]);
            acc += c[240 + 64 + k * 3 + dd] * __ldg(&W1[(32 + k) * 32 + o]);
            acc += c[480 + 64 + k * 3 + dd] * __ldg(&W1[(64 + k) * 32 + o]);
        }
        out[(size_t)g * FEAT + t] = acc * rsqrtf(96.f);
    } else {
        // group 2e: cat[48,5] @ W2[48,16] / sqrt(48)
        int cc = t - 160, o = cc / 5, dd = cc % 5;
        #pragma unroll 4
        for (int k = 0; k < 16; k++) {
            acc += c[160 + k * 5 + dd]       * __ldg(&W2[k * 16 + o]);
            acc += c[240 + 160 + k * 5 + dd] * __ldg(&W2[(16 + k) * 16 + o]);
            acc += c[480 + 160 + k * 5 + dd] * __ldg(&W2[(32 + k) * 16 + o]);
        }
        out[(size_t)g * FEAT + t] = acc * rsqrtf(48.f);
    }
}

// ---------------------------------------------------------------------------
// Launch: hist -> scan(+reset) -> scatter -> pool(x3000) -> final(x1000)
// ---------------------------------------------------------------------------
extern "C" void kernel_launch(void* const* d_in, const int* in_sizes, int n_in,
                              void* d_out, int out_size)
{
    const float* x     = nullptr;
    const int*   index = nullptr;
    const float *W0 = nullptr, *W1 = nullptr, *W2 = nullptr, *b0 = nullptr;

    for (int i = 0; i < n_in; i++) {
        switch (in_sizes[i]) {
            case 96000000: x     = (const float*)d_in[i]; break;
            case 400000:   index = (const int*)  d_in[i]; break;
            case 12288:    W0    = (const float*)d_in[i]; break;
            case 3072:     W1    = (const float*)d_in[i]; break;
            case 768:      W2    = (const float*)d_in[i]; break;
            case 64:       b0    = (const float*)d_in[i]; break;
            default: break;  // dim_size scalar etc.
        }
    }

    float* out = (float*)d_out;
    (void)out_size;

    k_hist   <<<(N_NODES + HIST_BLK * HIST_PER - 1) / (HIST_BLK * HIST_PER), HIST_BLK>>>(index);
    k_scan   <<<1, 1024>>>();
    k_scatter<<<(N_NODES + SCAT_SPAN - 1) / SCAT_SPAN, SCAT_BLK>>>(index);
    k_pool   <<<N_GRAPHS * SPLITS, 256>>>(x);
    k_final  <<<N_GRAPHS, 256>>>(W0, W1, W2, b0, out);
}